// round 17
// baseline (speedup 1.0000x reference)
#include <cuda_runtime.h>
#include <math.h>

#define NC        19
#define NIMG      4
#define HWN       589824          // 768*768
#define TOTAL_PIX 2359296
#define NB1       (256*NIMG)      // stats blocks
#define NB2       ((HWN/256)*NIMG)// main blocks = 9216

// ---------------- device scratch (static, no allocations) ----------------
// Replay-safe: the last-finishing block of each kernel consumes and re-zeroes
// the accumulators it read, so every launch (incl. graph replays) starts clean.
__device__ unsigned int  g_hist[NIMG][2][NC];   // [img][seg|att][class]
__device__ double        g_bce[2];              // pos,neg BCE sums
__device__ unsigned int  g_cnt[2];              // pos,neg counts
__device__ float         g_coefA[NIMG][NC];     // w_seg / den_seg     (overwritten)
__device__ float         g_coefB[NIMG][NC];     // 0.1*w_att/den_att   (overwritten)
__device__ double        g_edge;                // 0.3*weighted BCE    (overwritten)
__device__ double        g_accum;               // sum coef*logp
__device__ unsigned char g_pack[TOTAL_PIX];     // class|seg_valid<<5|att_valid<<6
__device__ unsigned int  g_done1, g_done2;      // completion counters (self-reset)

__device__ __forceinline__ float warp_sum_f(float x) {
#pragma unroll
    for (int o = 16; o > 0; o >>= 1) x += __shfl_down_sync(0xffffffffu, x, o);
    return x;
}
__device__ __forceinline__ unsigned warp_sum_u(unsigned x) {
#pragma unroll
    for (int o = 16; o > 0; o >>= 1) x += __shfl_down_sync(0xffffffffu, x, o);
    return x;
}

// ---------------- kernel 1: stats + pack; last block folds weights ----------------
// grid = (256, NIMG), block = 256. Each thread handles exactly 9 pixels.
__global__ void __launch_bounds__(256) stats_kernel(
        const float* __restrict__ edgein,
        const int*   __restrict__ segmask,
        const int*   __restrict__ edgemask) {
    const int n    = blockIdx.y;
    const int tid  = threadIdx.x;
    const int lane = tid & 31;
    const int warp = tid >> 5;
    const size_t base = (size_t)n * HWN;
    const int gid = blockIdx.x * 256 + tid;      // [0, 65536)

    __shared__ unsigned sh_hist[2 * NC];
    __shared__ float sh_bp[8], sh_bn[8];
    __shared__ unsigned sh_cp[8], sh_cn[8];

    if (tid < 2 * NC) sh_hist[tid] = 0u;
    __syncthreads();

    float bp = 0.f, bn = 0.f;
    unsigned cp = 0u, cn = 0u;

#pragma unroll 1
    for (int k = 0; k < 9; k++) {
        const size_t idx = base + (size_t)(k * 65536 + gid);   // < HWN exactly
        int   t  = segmask[idx];
        float e  = edgein [idx];
        int   em = edgemask[idx];

        bool inb = ((unsigned)t < (unsigned)NC);
        bool vs  = (t != 255);
        bool att = (e > 0.8f);
        bool va  = vs && att;
        int  tc  = min(max(t, 0), NC - 1);

        // one shared atomic per distinct class per warp
        unsigned mask = __match_any_sync(0xffffffffu, t);
        unsigned batt = __ballot_sync(0xffffffffu, att);
        bool leader = (lane == (__ffs(mask) - 1));
        if (leader && inb) {
            atomicAdd(&sh_hist[t], __popc(mask));
            unsigned ca = __popc(mask & batt);
            if (ca) atomicAdd(&sh_hist[NC + t], ca);
        }

        g_pack[idx] = (unsigned char)((unsigned)tc | (vs ? 32u : 0u) | (va ? 64u : 0u));

        float bce = fmaxf(e, 0.f) - e * (float)em + log1pf(__expf(-fabsf(e)));
        if (em == 1)      { bp += bce; cp++; }
        else if (em == 0) { bn += bce; cn++; }
    }

    bp = warp_sum_f(bp); bn = warp_sum_f(bn);
    cp = warp_sum_u(cp); cn = warp_sum_u(cn);
    if (lane == 0) { sh_bp[warp] = bp; sh_bn[warp] = bn; sh_cp[warp] = cp; sh_cn[warp] = cn; }
    __syncthreads();

    if (tid < 2 * NC) {
        unsigned v = sh_hist[tid];
        if (v) atomicAdd(&g_hist[n][tid / NC][tid % NC], v);
    }
    if (tid == 0) {
        float tbp = 0.f, tbn = 0.f; unsigned tcp = 0, tcn = 0;
#pragma unroll
        for (int w = 0; w < 8; w++) { tbp += sh_bp[w]; tbn += sh_bn[w]; tcp += sh_cp[w]; tcn += sh_cn[w]; }
        atomicAdd(&g_bce[0], (double)tbp);
        atomicAdd(&g_bce[1], (double)tbn);
        atomicAdd(&g_cnt[0], tcp);
        atomicAdd(&g_cnt[1], tcn);
    }

    // ---- last-block epilogue: compute coefficients ----
    __shared__ unsigned is_last;
    __threadfence();
    __syncthreads();
    if (tid == 0) is_last = (atomicAdd(&g_done1, 1u) == NB1 - 1u) ? 1u : 0u;
    __syncthreads();
    if (!is_last) return;

    {
        __shared__ double wseg[NIMG][NC], watt[NIMG][NC];
        __shared__ double den_seg[NIMG], den_att[NIMG];

        if (tid < NIMG * NC) {
            int m = tid / NC, c = tid % NC;
            double tot_s = 0.0, tot_a = 0.0;
            for (int cc = 0; cc < NC; cc++) {
                tot_s += (double)g_hist[m][0][cc];
                tot_a += (double)g_hist[m][1][cc];
            }
            double bs = (double)g_hist[m][0][c];
            double ba = (double)g_hist[m][1][c];
            wseg[m][c] = (bs != 0.0 ? (1.0 - bs / tot_s) : 0.0) + 1.0;
            watt[m][c] = (ba != 0.0 ? (1.0 - ba / tot_a) : 0.0) + 1.0;
        }
        __syncthreads();
        if (tid < NIMG) {
            double ds = 0.0, da = 0.0;
            for (int c = 0; c < NC; c++) {
                ds += (double)g_hist[tid][0][c] * wseg[tid][c];
                da += (double)g_hist[tid][1][c] * watt[tid][c];
            }
            den_seg[tid] = ds; den_att[tid] = da;
        }
        __syncthreads();
        if (tid < NIMG * NC) {
            int m = tid / NC, c = tid % NC;
            g_coefA[m][c] = (float)(wseg[m][c] / den_seg[m]);
            g_coefB[m][c] = (float)(0.1 * watt[m][c] / den_att[m]);
        }
        if (tid == 0) {
            double pos = (double)g_cnt[0], neg = (double)g_cnt[1];
            double s = pos + neg;
            g_edge = 0.3 * ((neg / s) * g_bce[0] + (pos / s) * g_bce[1]) / (double)TOTAL_PIX;
            g_bce[0] = 0.0; g_bce[1] = 0.0; g_cnt[0] = 0u; g_cnt[1] = 0u;
            g_done1 = 0u;                               // reset for next replay
        }
        __syncthreads();
        if (tid < NIMG * 2 * NC) ((unsigned*)g_hist)[tid] = 0u;   // re-zero
    }
}

// ---------------- kernel 2: main pass; last block writes the scalar ----------------
// grid = (2304, NIMG), block = 256 : one pixel per thread (R3 structure, 6.1 TB/s).
__global__ void __launch_bounds__(256) main_kernel(
        const float* __restrict__ segin,
        float* __restrict__ out) {
    const int n   = blockIdx.y;
    const int pix = blockIdx.x * 256 + threadIdx.x;   // < HWN exactly
    const size_t pb = (size_t)n * HWN + pix;
    const int tid = threadIdx.x;

    __shared__ float shA[NC], shB[NC];
    if (tid < NC) {
        shA[tid] = g_coefA[n][tid];
        shB[tid] = g_coefB[n][tid];
    }
    __syncthreads();

    const unsigned byte = (unsigned)g_pack[pb];
    const int t = (int)(byte & 31u);
    const float coeff = ((byte & 32u) ? shA[t] : 0.f)
                      + ((byte & 64u) ? shB[t] : 0.f);

    const float* sp = segin + (size_t)n * (NC * (size_t)HWN) + pix;

    float v[NC];
#pragma unroll
    for (int c = 0; c < NC; c++) v[c] = __ldg(sp + (size_t)c * HWN);

    float m = v[0];
#pragma unroll
    for (int c = 1; c < NC; c++) m = fmaxf(m, v[c]);

    float s = 0.f, vt = v[0];
#pragma unroll
    for (int c = 0; c < NC; c++) {
        s += __expf(v[c] - m);
        if (c == t) vt = v[c];
    }
    float contrib = coeff * (vt - m - __logf(s));

    __shared__ float sh_red[8];
    contrib = warp_sum_f(contrib);
    if ((tid & 31) == 0) sh_red[tid >> 5] = contrib;
    __syncthreads();
    if (tid == 0) {
        float bsum = 0.f;
#pragma unroll
        for (int w = 0; w < 8; w++) bsum += sh_red[w];
        atomicAdd(&g_accum, (double)bsum);
    }

    // ---- last-block epilogue: finalize scalar ----
    __shared__ unsigned is_last;
    __threadfence();
    __syncthreads();
    if (tid == 0) is_last = (atomicAdd(&g_done2, 1u) == NB2 - 1u) ? 1u : 0u;
    __syncthreads();
    if (is_last && tid == 0) {
        double a = atomicAdd(&g_accum, 0.0);          // coherent read
        out[0] = (float)(-a + g_edge);
        g_accum = 0.0;                                // reset for next replay
        g_done2 = 0u;
    }
}

// ---------------- launch: exactly two graph nodes ----------------
extern "C" void kernel_launch(void* const* d_in, const int* in_sizes, int n_in,
                              void* d_out, int out_size) {
    const float* segin    = (const float*)d_in[0];   // [4,19,768,768] f32
    const float* edgein   = (const float*)d_in[1];   // [4,1,768,768]  f32
    const int*   segmask  = (const int*)  d_in[2];   // [4,768,768]    i32
    const int*   edgemask = (const int*)  d_in[3];   // [4,1,768,768]  i32
    float* out = (float*)d_out;

    stats_kernel<<<dim3(256, NIMG), 256>>>(edgein, segmask, edgemask);
    main_kernel<<<dim3(HWN / 256, NIMG), 256>>>(segin, out);
}